// round 12
// baseline (speedup 1.0000x reference)
#include <cuda_runtime.h>
#include <cuda_bf16.h>
#include <cstdint>

#define NMAX 50000
#define EMAX 660000
#define HD   128

// ---------------- device scratch ----------------
__device__ __align__(16) float g_h[NMAX * HD];
__device__ __align__(16) float g_agg[NMAX * HD];
__device__ __align__(16) float g_ssrc[NMAX];
__device__ __align__(16) float g_sdst[NMAX];
__device__ __align__(16) int   g_cnt[NMAX];
__device__ __align__(16) int   g_wptr[NMAX];
__device__ __align__(16) int   g_rowptr[NMAX + 1];
__device__ __align__(16) int   g_col[EMAX];
__device__ __align__(16) int   g_bsum[256];
__device__ __align__(16) int   g_boff[256];
// B fragments in mma order: [nb][ks][lane] -> {bhi0, bhi1, blo0, blo1}
__device__ uint4 g_bf0[16 * 8 * 32];
__device__ uint4 g_bf1[16 * 8 * 32];
__device__ uint4 g_bf2[8 * 8 * 32];

__device__ __forceinline__ uint32_t smem_u32(const void* p) {
    uint32_t a;
    asm("{ .reg .u64 t; cvta.to.shared.u64 t, %1; cvt.u32.u64 %0, t; }" : "=r"(a) : "l"(p));
    return a;
}
__device__ __forceinline__ void ldmatrix_x4(uint32_t* r, uint32_t addr) {
    asm volatile("ldmatrix.sync.aligned.m8n8.x4.shared.b16 {%0,%1,%2,%3}, [%4];"
                 : "=r"(r[0]), "=r"(r[1]), "=r"(r[2]), "=r"(r[3]) : "r"(addr));
}
__device__ __forceinline__ void mma16816(float* c, const uint32_t* a, uint32_t b0, uint32_t b1) {
    asm volatile(
        "mma.sync.aligned.m16n8k16.row.col.f32.bf16.bf16.f32 "
        "{%0,%1,%2,%3}, {%4,%5,%6,%7}, {%8,%9}, {%0,%1,%2,%3};"
        : "+f"(c[0]), "+f"(c[1]), "+f"(c[2]), "+f"(c[3])
        : "r"(a[0]), "r"(a[1]), "r"(a[2]), "r"(a[3]), "r"(b0), "r"(b1));
}
__device__ __forceinline__ uint32_t pack_hi(float a, float b) {
    __nv_bfloat162 h = __floats2bfloat162_rn(a, b);
    return *(uint32_t*)&h;
}

// ---------------- CSR build ----------------
__global__ void zero_kernel(int n) {
    int i = blockIdx.x * blockDim.x + threadIdx.x;
    if (i < n) g_cnt[i] = 0;
}
__global__ void hist_kernel(const int* __restrict__ dst, int E) {
    int b = (blockIdx.x * blockDim.x + threadIdx.x) * 4;
    #pragma unroll
    for (int j = 0; j < 4; j++)
        if (b + j < E) atomicAdd(&g_cnt[dst[b + j]], 1);
}

// ---- 3-phase parallel scan over vals[i] = cnt[i] + 1 ----
__device__ __forceinline__ int block_scan_excl(int val, int tid, int* total) {
    __shared__ int wsum[8];
    int lane = tid & 31, warp = tid >> 5;
    int v = val;
    #pragma unroll
    for (int o = 1; o < 32; o <<= 1) {
        int u = __shfl_up_sync(0xffffffffu, v, o);
        if (lane >= o) v += u;
    }
    if (lane == 31) wsum[warp] = v;
    __syncthreads();
    if (tid < 8) {
        int w = wsum[tid];
        #pragma unroll
        for (int o = 1; o < 8; o <<= 1) {
            int u = __shfl_up_sync(0xffu, w, o);
            if (tid >= o) w += u;
        }
        wsum[tid] = w;
    }
    __syncthreads();
    int excl = v - val + (warp ? wsum[warp - 1] : 0);
    if (total) *total = wsum[7];
    return excl;
}

__global__ __launch_bounds__(256) void scan_reduce(int n) {
    int i = blockIdx.x * 256 + threadIdx.x;
    int val = (i < n) ? (g_cnt[i] + 1) : 0;
    #pragma unroll
    for (int o = 16; o; o >>= 1) val += __shfl_xor_sync(0xffffffffu, val, o);
    __shared__ int ws[8];
    if ((threadIdx.x & 31) == 0) ws[threadIdx.x >> 5] = val;
    __syncthreads();
    if (threadIdx.x == 0) {
        int s = 0;
        #pragma unroll
        for (int w = 0; w < 8; w++) s += ws[w];
        g_bsum[blockIdx.x] = s;
    }
}
__global__ __launch_bounds__(256) void scan_bsums(int nb, int n) {
    int tid = threadIdx.x;
    int val = (tid < nb) ? g_bsum[tid] : 0;
    int total;
    int excl = block_scan_excl(val, tid, &total);
    if (tid < nb) g_boff[tid] = excl;
    if (tid == 0) g_rowptr[n] = total;
}
__global__ __launch_bounds__(256) void scan_write(int n) {
    int i = blockIdx.x * 256 + threadIdx.x;
    int val = (i < n) ? (g_cnt[i] + 1) : 0;
    int excl = block_scan_excl(val, threadIdx.x, nullptr);
    if (i < n) {
        int p = g_boff[blockIdx.x] + excl;
        g_rowptr[i] = p;
        g_wptr[i] = p;
    }
}

__global__ void fill_kernel(const int* __restrict__ src, const int* __restrict__ dst,
                            int E, int n) {
    int b = (blockIdx.x * blockDim.x + threadIdx.x) * 4;
    #pragma unroll
    for (int j = 0; j < 4; j++) {
        int i = b + j;
        if (i < E) {
            int p = atomicAdd(&g_wptr[dst[i]], 1);
            g_col[p] = src[i];
        } else if (i < E + n) {
            int vtx = i - E;
            int p = atomicAdd(&g_wptr[vtx], 1);
            g_col[p] = vtx;
        }
    }
}

// ---------------- W prep: pack B fragments (hi/lo bf16 split) ----------------
__global__ void wprep_kernel(const float* __restrict__ W0, const float* __restrict__ W1,
                             const float* __restrict__ W2) {
    int idx = blockIdx.x * blockDim.x + threadIdx.x;
    const float* W;
    uint4* out;
    int N, local;
    if (idx < 4096)       { W = W0; out = g_bf0; N = 128; local = idx; }
    else if (idx < 8192)  { W = W1; out = g_bf1; N = 128; local = idx - 4096; }
    else if (idx < 10240) { W = W2; out = g_bf2; N = 64;  local = idx - 8192; }
    else return;
    int lane = local & 31;
    int ks = (local >> 5) & 7;
    int nb = local >> 8;
    int g = lane >> 2, t = lane & 3;
    int nn = nb * 8 + g;
    int k0 = ks * 16 + t * 2;
    float w00 = W[(k0 + 0) * N + nn], w01 = W[(k0 + 1) * N + nn];
    float w10 = W[(k0 + 8) * N + nn], w11 = W[(k0 + 9) * N + nn];
    __nv_bfloat16 h00 = __float2bfloat16(w00), h01 = __float2bfloat16(w01);
    __nv_bfloat16 h10 = __float2bfloat16(w10), h11 = __float2bfloat16(w11);
    uint4 o;
    o.x = pack_hi(w00, w01);
    o.y = pack_hi(w10, w11);
    o.z = pack_hi(w00 - __bfloat162float(h00), w01 - __bfloat162float(h01));
    o.w = pack_hi(w10 - __bfloat162float(h10), w11 - __bfloat162float(h11));
    out[local] = o;
}

// ---------------- bf16 mma GEMM + fused attention-score epilogue ----------------
__device__ __forceinline__ float silu(float v) { return v / (1.0f + __expf(-v)); }

template<int DOUT, bool ACT>
__global__ __launch_bounds__(256) void gemm_mma(
    const float* __restrict__ X, const uint4* __restrict__ Bf,
    const float* __restrict__ bin,
    const float* __restrict__ av_s, const float* __restrict__ av_d,
    float* __restrict__ O, int n)
{
    constexpr int NSTEP = DOUT / 8;
    constexpr int AST = 136;
    extern __shared__ __align__(16) char smem[];
    __nv_bfloat16* Ahi = (__nv_bfloat16*)smem;
    __nv_bfloat16* Alo = Ahi + 128 * AST;

    const int tid = threadIdx.x;
    const int wid = tid >> 5;
    const int lane = tid & 31;
    const int row0 = blockIdx.x * 128;

    for (int i = tid; i < 4096; i += 256) {
        int row = i >> 5, c4 = (i & 31) * 4;
        float4 v = make_float4(0.f, 0.f, 0.f, 0.f);
        if (row0 + row < n) v = *(const float4*)(X + (size_t)(row0 + row) * HD + c4);
        if (ACT) {
            v.x = silu(v.x + bin[c4 + 0]);
            v.y = silu(v.y + bin[c4 + 1]);
            v.z = silu(v.z + bin[c4 + 2]);
            v.w = silu(v.w + bin[c4 + 3]);
        }
        __nv_bfloat162 h01 = __floats2bfloat162_rn(v.x, v.y);
        __nv_bfloat162 h23 = __floats2bfloat162_rn(v.z, v.w);
        __nv_bfloat162 l01 = __floats2bfloat162_rn(v.x - __low2float(h01), v.y - __high2float(h01));
        __nv_bfloat162 l23 = __floats2bfloat162_rn(v.z - __low2float(h23), v.w - __high2float(h23));
        *(__nv_bfloat162*)(Ahi + row * AST + c4)     = h01;
        *(__nv_bfloat162*)(Ahi + row * AST + c4 + 2) = h23;
        *(__nv_bfloat162*)(Alo + row * AST + c4)     = l01;
        *(__nv_bfloat162*)(Alo + row * AST + c4 + 2) = l23;
    }
    __syncthreads();

    float acc[NSTEP][4];
    #pragma unroll
    for (int i = 0; i < NSTEP; i++) {
        acc[i][0] = acc[i][1] = acc[i][2] = acc[i][3] = 0.f;
    }

    const int arow = 16 * wid + (lane & 15);
    const int acol = (lane >> 4) * 8;
    const uint32_t ahi_base = smem_u32(Ahi + arow * AST + acol);
    const uint32_t alo_base = smem_u32(Alo + arow * AST + acol);

    #pragma unroll
    for (int ks = 0; ks < 8; ks++) {
        uint32_t ahi[4], alo[4];
        ldmatrix_x4(ahi, ahi_base + ks * 32);
        ldmatrix_x4(alo, alo_base + ks * 32);
        #pragma unroll
        for (int nb = 0; nb < NSTEP; nb++) {
            uint4 b = __ldg(&Bf[(nb * 8 + ks) * 32 + lane]);
            mma16816(acc[nb], ahi, b.x, b.y);
            mma16816(acc[nb], ahi, b.z, b.w);
            mma16816(acc[nb], alo, b.x, b.y);
        }
    }

    const int g = lane >> 2, t = lane & 3;
    const int r0 = row0 + 16 * wid + g;
    const int r1 = r0 + 8;
    float ss0 = 0.f, sd0 = 0.f, ss1 = 0.f, sd1 = 0.f;
    #pragma unroll
    for (int nb = 0; nb < NSTEP; nb++) {
        int c = nb * 8 + t * 2;
        float a0 = __ldg(&av_s[c]), a1 = __ldg(&av_s[c + 1]);
        float d0 = __ldg(&av_d[c]), d1 = __ldg(&av_d[c + 1]);
        ss0 += acc[nb][0] * a0 + acc[nb][1] * a1;
        sd0 += acc[nb][0] * d0 + acc[nb][1] * d1;
        ss1 += acc[nb][2] * a0 + acc[nb][3] * a1;
        sd1 += acc[nb][2] * d0 + acc[nb][3] * d1;
        if (r0 < n) *(float2*)(O + (size_t)r0 * DOUT + c) = make_float2(acc[nb][0], acc[nb][1]);
        if (r1 < n) *(float2*)(O + (size_t)r1 * DOUT + c) = make_float2(acc[nb][2], acc[nb][3]);
    }
    #pragma unroll
    for (int o = 1; o <= 2; o <<= 1) {
        ss0 += __shfl_xor_sync(0xffffffffu, ss0, o);
        sd0 += __shfl_xor_sync(0xffffffffu, sd0, o);
        ss1 += __shfl_xor_sync(0xffffffffu, ss1, o);
        sd1 += __shfl_xor_sync(0xffffffffu, sd1, o);
    }
    if (t == 0) {
        if (r0 < n) { g_ssrc[r0] = ss0; g_sdst[r0] = sd0; }
        if (r1 < n) { g_ssrc[r1] = ss1; g_sdst[r1] = sd1; }
    }
}

// -------- aggregation, 128-wide layers: 2 warps per node (64 feats each) --------
__global__ __launch_bounds__(256) void agg2_kernel(const float* __restrict__ Hin,
    float* __restrict__ out, int n)
{
    int gw = (blockIdx.x * blockDim.x + threadIdx.x) >> 5;
    int node = gw >> 1;
    int half = gw & 1;
    int lane = threadIdx.x & 31;
    if (node >= n) return;
    int beg = g_rowptr[node], end = g_rowptr[node + 1];
    float sd = g_sdst[node];

    float m = g_ssrc[node] + sd;
    m = m > 0.f ? m : 0.2f * m;

    const float* Hb = Hin + half * 64 + lane * 2;
    float a0 = 0.f, a1 = 0.f, denom = 0.f;

    int j = beg;
    for (; j + 3 < end; j += 4) {
        int s0 = g_col[j], s1 = g_col[j + 1], s2 = g_col[j + 2], s3 = g_col[j + 3];
        float v0 = g_ssrc[s0], v1 = g_ssrc[s1], v2 = g_ssrc[s2], v3 = g_ssrc[s3];
        float2 h0 = *(const float2*)(Hb + (size_t)s0 * 128);
        float2 h1 = *(const float2*)(Hb + (size_t)s1 * 128);
        float2 h2 = *(const float2*)(Hb + (size_t)s2 * 128);
        float2 h3 = *(const float2*)(Hb + (size_t)s3 * 128);
        v0 += sd; v1 += sd; v2 += sd; v3 += sd;
        v0 = v0 > 0.f ? v0 : 0.2f * v0;
        v1 = v1 > 0.f ? v1 : 0.2f * v1;
        v2 = v2 > 0.f ? v2 : 0.2f * v2;
        v3 = v3 > 0.f ? v3 : 0.2f * v3;
        float e0 = __expf(v0 - m), e1 = __expf(v1 - m);
        float e2 = __expf(v2 - m), e3 = __expf(v3 - m);
        denom += (e0 + e1) + (e2 + e3);
        a0 += e0 * h0.x + e1 * h1.x + e2 * h2.x + e3 * h3.x;
        a1 += e0 * h0.y + e1 * h1.y + e2 * h2.y + e3 * h3.y;
    }
    for (; j < end; j++) {
        int s0 = g_col[j];
        float v0 = g_ssrc[s0] + sd;
        v0 = v0 > 0.f ? v0 : 0.2f * v0;
        float e0 = __expf(v0 - m);
        denom += e0;
        float2 h0 = *(const float2*)(Hb + (size_t)s0 * 128);
        a0 += e0 * h0.x;
        a1 += e0 * h0.y;
    }
    float inv = 1.0f / denom;
    *(float2*)(out + (size_t)node * 128 + half * 64 + lane * 2) =
        make_float2(a0 * inv, a1 * inv);
}

// -------- final aggregation (64-wide) + bias + log_softmax: 1 warp per node --------
__global__ __launch_bounds__(256) void aggf_kernel(const float* __restrict__ Hin,
    float* __restrict__ out, const float* __restrict__ bias, int n)
{
    int gw = (blockIdx.x * blockDim.x + threadIdx.x) >> 5;
    int lane = threadIdx.x & 31;
    if (gw >= n) return;
    int beg = g_rowptr[gw], end = g_rowptr[gw + 1];
    float sd = g_sdst[gw];

    float m = g_ssrc[gw] + sd;
    m = m > 0.f ? m : 0.2f * m;

    float a0 = 0.f, a1 = 0.f, denom = 0.f;
    int j = beg;
    for (; j + 3 < end; j += 4) {
        int s0 = g_col[j], s1 = g_col[j + 1], s2 = g_col[j + 2], s3 = g_col[j + 3];
        float v0 = g_ssrc[s0], v1 = g_ssrc[s1], v2 = g_ssrc[s2], v3 = g_ssrc[s3];
        float2 h0 = *(const float2*)(Hin + (size_t)s0 * 64 + lane * 2);
        float2 h1 = *(const float2*)(Hin + (size_t)s1 * 64 + lane * 2);
        float2 h2 = *(const float2*)(Hin + (size_t)s2 * 64 + lane * 2);
        float2 h3 = *(const float2*)(Hin + (size_t)s3 * 64 + lane * 2);
        v0 += sd; v1 += sd; v2 += sd; v3 += sd;
        v0 = v0 > 0.f ? v0 : 0.2f * v0;
        v1 = v1 > 0.f ? v1 : 0.2f * v1;
        v2 = v2 > 0.f ? v2 : 0.2f * v2;
        v3 = v3 > 0.f ? v3 : 0.2f * v3;
        float e0 = __expf(v0 - m), e1 = __expf(v1 - m);
        float e2 = __expf(v2 - m), e3 = __expf(v3 - m);
        denom += (e0 + e1) + (e2 + e3);
        a0 += e0 * h0.x + e1 * h1.x + e2 * h2.x + e3 * h3.x;
        a1 += e0 * h0.y + e1 * h1.y + e2 * h2.y + e3 * h3.y;
    }
    for (; j < end; j++) {
        int s0 = g_col[j];
        float v0 = g_ssrc[s0] + sd;
        v0 = v0 > 0.f ? v0 : 0.2f * v0;
        float e0 = __expf(v0 - m);
        denom += e0;
        float2 h0 = *(const float2*)(Hin + (size_t)s0 * 64 + lane * 2);
        a0 += e0 * h0.x;
        a1 += e0 * h0.y;
    }
    float inv = 1.0f / denom;

    float2 bb = *(const float2*)(bias + lane * 2);
    float x0 = a0 * inv + bb.x;
    float x1 = a1 * inv + bb.y;
    float mm = fmaxf(x0, x1);
    #pragma unroll
    for (int o = 16; o; o >>= 1) mm = fmaxf(mm, __shfl_xor_sync(0xffffffffu, mm, o));
    float s = __expf(x0 - mm) + __expf(x1 - mm);
    #pragma unroll
    for (int o = 16; o; o >>= 1) s += __shfl_xor_sync(0xffffffffu, s, o);
    float lse = mm + __logf(s);
    *(float2*)(out + (size_t)gw * 64 + lane * 2) = make_float2(x0 - lse, x1 - lse);
}

// ---------------- launch ----------------
extern "C" void kernel_launch(void* const* d_in, const int* in_sizes, int n_in,
                              void* d_out, int out_size)
{
    const float* x   = (const float*)d_in[0];
    const int*   ei  = (const int*)d_in[1];
    const float* W0  = (const float*)d_in[2];
    const float* as0 = (const float*)d_in[3];
    const float* ad0 = (const float*)d_in[4];
    const float* b0  = (const float*)d_in[5];
    const float* W1  = (const float*)d_in[6];
    const float* as1 = (const float*)d_in[7];
    const float* ad1 = (const float*)d_in[8];
    const float* b1  = (const float*)d_in[9];
    const float* W2  = (const float*)d_in[10];
    const float* as2 = (const float*)d_in[11];
    const float* ad2 = (const float*)d_in[12];
    const float* b2  = (const float*)d_in[13];

    int n = in_sizes[0] / HD;
    int E = in_sizes[1] / 2;
    const int* src = ei;
    const int* dst = ei + E;

    float *h = nullptr, *agg = nullptr;
    uint4 *bf0, *bf1, *bf2;
    cudaGetSymbolAddress((void**)&h, g_h);
    cudaGetSymbolAddress((void**)&agg, g_agg);
    cudaGetSymbolAddress((void**)&bf0, g_bf0);
    cudaGetSymbolAddress((void**)&bf1, g_bf1);
    cudaGetSymbolAddress((void**)&bf2, g_bf2);

    const int smemA = 2 * 128 * 136 * 2;   // 69632 bytes
    cudaFuncSetAttribute(gemm_mma<128, false>, cudaFuncAttributeMaxDynamicSharedMemorySize, smemA);
    cudaFuncSetAttribute(gemm_mma<128, true>,  cudaFuncAttributeMaxDynamicSharedMemorySize, smemA);
    cudaFuncSetAttribute(gemm_mma<64, true>,   cudaFuncAttributeMaxDynamicSharedMemorySize, smemA);

    wprep_kernel<<<40, 256>>>(W0, W1, W2);

    int nb = (n + 255) / 256;
    zero_kernel<<<(n + 255) / 256, 256>>>(n);
    hist_kernel<<<(E / 4 + 255) / 256, 256>>>(dst, E);
    scan_reduce<<<nb, 256>>>(n);
    scan_bsums<<<1, 256>>>(nb, n);
    scan_write<<<nb, 256>>>(n);
    fill_kernel<<<((E + n + 3) / 4 + 255) / 256, 256>>>(src, dst, E, n);

    int gemmg = (n + 127) / 128;
    int warpg  = (n * 32 + 255) / 256;       // 1 warp / node
    int warpg2 = (n * 64 + 255) / 256;       // 2 warps / node

    gemm_mma<128, false><<<gemmg, 256, smemA>>>(x, bf0, nullptr, as0, ad0, h, n);
    agg2_kernel<<<warpg2, 256>>>(h, agg, n);

    gemm_mma<128, true><<<gemmg, 256, smemA>>>(agg, bf1, b0, as1, ad1, h, n);
    agg2_kernel<<<warpg2, 256>>>(h, agg, n);

    gemm_mma<64, true><<<gemmg, 256, smemA>>>(agg, bf2, b1, as2, ad2, h, n);
    aggf_kernel<<<warpg, 256>>>(h, (float*)d_out, b2, n);
}

// round 14
// speedup vs baseline: 1.1645x; 1.1645x over previous
#include <cuda_runtime.h>
#include <cuda_bf16.h>
#include <cuda_fp16.h>
#include <cstdint>

#define NMAX 50000
#define EMAX 660000
#define HD   128

// ---------------- device scratch ----------------
__device__ __align__(16) __half g_h[NMAX * HD];     // fp16: only consumed by agg gather
__device__ __align__(16) float g_agg[NMAX * HD];
__device__ __align__(16) float g_ssrc[NMAX];
__device__ __align__(16) float g_sdst[NMAX];
__device__ __align__(16) int   g_cnt[NMAX];
__device__ __align__(16) int   g_wptr[NMAX];
__device__ __align__(16) int   g_rowptr[NMAX + 1];
__device__ __align__(16) int   g_col[EMAX];
__device__ __align__(16) int   g_bsum[256];
__device__ __align__(16) int   g_boff[256];
// B fragments in mma order: [nb][ks][lane] -> {bhi0, bhi1, blo0, blo1}
__device__ uint4 g_bf0[16 * 8 * 32];
__device__ uint4 g_bf1[16 * 8 * 32];
__device__ uint4 g_bf2[8 * 8 * 32];

__device__ __forceinline__ uint32_t smem_u32(const void* p) {
    uint32_t a;
    asm("{ .reg .u64 t; cvta.to.shared.u64 t, %1; cvt.u32.u64 %0, t; }" : "=r"(a) : "l"(p));
    return a;
}
__device__ __forceinline__ void ldmatrix_x4(uint32_t* r, uint32_t addr) {
    asm volatile("ldmatrix.sync.aligned.m8n8.x4.shared.b16 {%0,%1,%2,%3}, [%4];"
                 : "=r"(r[0]), "=r"(r[1]), "=r"(r[2]), "=r"(r[3]) : "r"(addr));
}
__device__ __forceinline__ void mma16816(float* c, const uint32_t* a, uint32_t b0, uint32_t b1) {
    asm volatile(
        "mma.sync.aligned.m16n8k16.row.col.f32.bf16.bf16.f32 "
        "{%0,%1,%2,%3}, {%4,%5,%6,%7}, {%8,%9}, {%0,%1,%2,%3};"
        : "+f"(c[0]), "+f"(c[1]), "+f"(c[2]), "+f"(c[3])
        : "r"(a[0]), "r"(a[1]), "r"(a[2]), "r"(a[3]), "r"(b0), "r"(b1));
}
__device__ __forceinline__ uint32_t pack_hi(float a, float b) {
    __nv_bfloat162 h = __floats2bfloat162_rn(a, b);
    return *(uint32_t*)&h;
}

// ---------------- CSR build ----------------
__global__ void zero_kernel(int n) {
    int i = blockIdx.x * blockDim.x + threadIdx.x;
    if (i < n) g_cnt[i] = 0;
}
__global__ void hist_kernel(const int* __restrict__ dst, int E) {
    int b = (blockIdx.x * blockDim.x + threadIdx.x) * 4;
    #pragma unroll
    for (int j = 0; j < 4; j++)
        if (b + j < E) atomicAdd(&g_cnt[dst[b + j]], 1);
}

// ---- 3-phase parallel scan over vals[i] = cnt[i] + 1 ----
__device__ __forceinline__ int block_scan_excl(int val, int tid, int* total) {
    __shared__ int wsum[8];
    int lane = tid & 31, warp = tid >> 5;
    int v = val;
    #pragma unroll
    for (int o = 1; o < 32; o <<= 1) {
        int u = __shfl_up_sync(0xffffffffu, v, o);
        if (lane >= o) v += u;
    }
    if (lane == 31) wsum[warp] = v;
    __syncthreads();
    if (tid < 8) {
        int w = wsum[tid];
        #pragma unroll
        for (int o = 1; o < 8; o <<= 1) {
            int u = __shfl_up_sync(0xffu, w, o);
            if (tid >= o) w += u;
        }
        wsum[tid] = w;
    }
    __syncthreads();
    int excl = v - val + (warp ? wsum[warp - 1] : 0);
    if (total) *total = wsum[7];
    return excl;
}

__global__ __launch_bounds__(256) void scan_reduce(int n) {
    int i = blockIdx.x * 256 + threadIdx.x;
    int val = (i < n) ? (g_cnt[i] + 1) : 0;
    #pragma unroll
    for (int o = 16; o; o >>= 1) val += __shfl_xor_sync(0xffffffffu, val, o);
    __shared__ int ws[8];
    if ((threadIdx.x & 31) == 0) ws[threadIdx.x >> 5] = val;
    __syncthreads();
    if (threadIdx.x == 0) {
        int s = 0;
        #pragma unroll
        for (int w = 0; w < 8; w++) s += ws[w];
        g_bsum[blockIdx.x] = s;
    }
}
__global__ __launch_bounds__(256) void scan_bsums(int nb, int n) {
    int tid = threadIdx.x;
    int val = (tid < nb) ? g_bsum[tid] : 0;
    int total;
    int excl = block_scan_excl(val, tid, &total);
    if (tid < nb) g_boff[tid] = excl;
    if (tid == 0) g_rowptr[n] = total;
}
__global__ __launch_bounds__(256) void scan_write(int n) {
    int i = blockIdx.x * 256 + threadIdx.x;
    int val = (i < n) ? (g_cnt[i] + 1) : 0;
    int excl = block_scan_excl(val, threadIdx.x, nullptr);
    if (i < n) {
        int p = g_boff[blockIdx.x] + excl;
        g_rowptr[i] = p;
        g_wptr[i] = p;
    }
}

__global__ void fill_kernel(const int* __restrict__ src, const int* __restrict__ dst,
                            int E, int n) {
    int b = (blockIdx.x * blockDim.x + threadIdx.x) * 4;
    #pragma unroll
    for (int j = 0; j < 4; j++) {
        int i = b + j;
        if (i < E) {
            int p = atomicAdd(&g_wptr[dst[i]], 1);
            g_col[p] = src[i];
        } else if (i < E + n) {
            int vtx = i - E;
            int p = atomicAdd(&g_wptr[vtx], 1);
            g_col[p] = vtx;
        }
    }
}

// ---------------- W prep: pack B fragments (hi/lo bf16 split) ----------------
__global__ void wprep_kernel(const float* __restrict__ W0, const float* __restrict__ W1,
                             const float* __restrict__ W2) {
    int idx = blockIdx.x * blockDim.x + threadIdx.x;
    const float* W;
    uint4* out;
    int N, local;
    if (idx < 4096)       { W = W0; out = g_bf0; N = 128; local = idx; }
    else if (idx < 8192)  { W = W1; out = g_bf1; N = 128; local = idx - 4096; }
    else if (idx < 10240) { W = W2; out = g_bf2; N = 64;  local = idx - 8192; }
    else return;
    int lane = local & 31;
    int ks = (local >> 5) & 7;
    int nb = local >> 8;
    int g = lane >> 2, t = lane & 3;
    int nn = nb * 8 + g;
    int k0 = ks * 16 + t * 2;
    float w00 = W[(k0 + 0) * N + nn], w01 = W[(k0 + 1) * N + nn];
    float w10 = W[(k0 + 8) * N + nn], w11 = W[(k0 + 9) * N + nn];
    __nv_bfloat16 h00 = __float2bfloat16(w00), h01 = __float2bfloat16(w01);
    __nv_bfloat16 h10 = __float2bfloat16(w10), h11 = __float2bfloat16(w11);
    uint4 o;
    o.x = pack_hi(w00, w01);
    o.y = pack_hi(w10, w11);
    o.z = pack_hi(w00 - __bfloat162float(h00), w01 - __bfloat162float(h01));
    o.w = pack_hi(w10 - __bfloat162float(h10), w11 - __bfloat162float(h11));
    out[local] = o;
}

// ---------------- bf16 mma GEMM + fused attention-score epilogue ----------------
__device__ __forceinline__ float silu(float v) { return v / (1.0f + __expf(-v)); }

// O is fp16 (consumed only by agg gather); scores from fp32 accumulators.
template<int DOUT, bool ACT>
__global__ __launch_bounds__(256) void gemm_mma(
    const float* __restrict__ X, const uint4* __restrict__ Bf,
    const float* __restrict__ bin,
    const float* __restrict__ av_s, const float* __restrict__ av_d,
    __half* __restrict__ O, int n)
{
    constexpr int NSTEP = DOUT / 8;
    constexpr int AST = 136;
    extern __shared__ __align__(16) char smem[];
    __nv_bfloat16* Ahi = (__nv_bfloat16*)smem;
    __nv_bfloat16* Alo = Ahi + 128 * AST;

    const int tid = threadIdx.x;
    const int wid = tid >> 5;
    const int lane = tid & 31;
    const int row0 = blockIdx.x * 128;

    for (int i = tid; i < 4096; i += 256) {
        int row = i >> 5, c4 = (i & 31) * 4;
        float4 v = make_float4(0.f, 0.f, 0.f, 0.f);
        if (row0 + row < n) v = *(const float4*)(X + (size_t)(row0 + row) * HD + c4);
        if (ACT) {
            v.x = silu(v.x + bin[c4 + 0]);
            v.y = silu(v.y + bin[c4 + 1]);
            v.z = silu(v.z + bin[c4 + 2]);
            v.w = silu(v.w + bin[c4 + 3]);
        }
        __nv_bfloat162 h01 = __floats2bfloat162_rn(v.x, v.y);
        __nv_bfloat162 h23 = __floats2bfloat162_rn(v.z, v.w);
        __nv_bfloat162 l01 = __floats2bfloat162_rn(v.x - __low2float(h01), v.y - __high2float(h01));
        __nv_bfloat162 l23 = __floats2bfloat162_rn(v.z - __low2float(h23), v.w - __high2float(h23));
        *(__nv_bfloat162*)(Ahi + row * AST + c4)     = h01;
        *(__nv_bfloat162*)(Ahi + row * AST + c4 + 2) = h23;
        *(__nv_bfloat162*)(Alo + row * AST + c4)     = l01;
        *(__nv_bfloat162*)(Alo + row * AST + c4 + 2) = l23;
    }
    __syncthreads();

    float acc[NSTEP][4];
    #pragma unroll
    for (int i = 0; i < NSTEP; i++) {
        acc[i][0] = acc[i][1] = acc[i][2] = acc[i][3] = 0.f;
    }

    const int arow = 16 * wid + (lane & 15);
    const int acol = (lane >> 4) * 8;
    const uint32_t ahi_base = smem_u32(Ahi + arow * AST + acol);
    const uint32_t alo_base = smem_u32(Alo + arow * AST + acol);

    #pragma unroll
    for (int ks = 0; ks < 8; ks++) {
        uint32_t ahi[4], alo[4];
        ldmatrix_x4(ahi, ahi_base + ks * 32);
        ldmatrix_x4(alo, alo_base + ks * 32);
        #pragma unroll
        for (int nb = 0; nb < NSTEP; nb++) {
            uint4 b = __ldg(&Bf[(nb * 8 + ks) * 32 + lane]);
            mma16816(acc[nb], ahi, b.x, b.y);
            mma16816(acc[nb], ahi, b.z, b.w);
            mma16816(acc[nb], alo, b.x, b.y);
        }
    }

    const int g = lane >> 2, t = lane & 3;
    const int r0 = row0 + 16 * wid + g;
    const int r1 = r0 + 8;
    float ss0 = 0.f, sd0 = 0.f, ss1 = 0.f, sd1 = 0.f;
    #pragma unroll
    for (int nb = 0; nb < NSTEP; nb++) {
        int c = nb * 8 + t * 2;
        float a0 = __ldg(&av_s[c]), a1 = __ldg(&av_s[c + 1]);
        float d0 = __ldg(&av_d[c]), d1 = __ldg(&av_d[c + 1]);
        ss0 += acc[nb][0] * a0 + acc[nb][1] * a1;
        sd0 += acc[nb][0] * d0 + acc[nb][1] * d1;
        ss1 += acc[nb][2] * a0 + acc[nb][3] * a1;
        sd1 += acc[nb][2] * d0 + acc[nb][3] * d1;
        if (r0 < n) *(__half2*)(O + (size_t)r0 * DOUT + c) = __floats2half2_rn(acc[nb][0], acc[nb][1]);
        if (r1 < n) *(__half2*)(O + (size_t)r1 * DOUT + c) = __floats2half2_rn(acc[nb][2], acc[nb][3]);
    }
    #pragma unroll
    for (int o = 1; o <= 2; o <<= 1) {
        ss0 += __shfl_xor_sync(0xffffffffu, ss0, o);
        sd0 += __shfl_xor_sync(0xffffffffu, sd0, o);
        ss1 += __shfl_xor_sync(0xffffffffu, ss1, o);
        sd1 += __shfl_xor_sync(0xffffffffu, sd1, o);
    }
    if (t == 0) {
        if (r0 < n) { g_ssrc[r0] = ss0; g_sdst[r0] = sd0; }
        if (r1 < n) { g_ssrc[r1] = ss1; g_sdst[r1] = sd1; }
    }
}

// ---------------- aggregation: single pass, 4-edge batches, fp16 gathers ----------------
template<int DOUT, bool FINAL>
__global__ __launch_bounds__(256) void agg_kernel(const __half* __restrict__ Hin,
    float* __restrict__ out, const float* __restrict__ bias, int n)
{
    int gw = (blockIdx.x * blockDim.x + threadIdx.x) >> 5;
    int lane = threadIdx.x & 31;
    if (gw >= n) return;
    int beg = g_rowptr[gw], end = g_rowptr[gw + 1];
    float sd = g_sdst[gw];

    // stabilizer: this node's self-loop score (always a member of the max-set)
    float m = g_ssrc[gw] + sd;
    m = m > 0.f ? m : 0.2f * m;

    constexpr int V = DOUT / 32;     // floats per lane: 4 (128) or 2 (64)
    float acc[V];
    #pragma unroll
    for (int t = 0; t < V; t++) acc[t] = 0.f;
    float denom = 0.f;

    int j = beg;
    for (; j + 3 < end; j += 4) {
        int s0 = g_col[j], s1 = g_col[j + 1], s2 = g_col[j + 2], s3 = g_col[j + 3];
        float v0 = g_ssrc[s0], v1 = g_ssrc[s1], v2 = g_ssrc[s2], v3 = g_ssrc[s3];
        if constexpr (V == 4) {
            uint2 r0 = *(const uint2*)(Hin + (size_t)s0 * DOUT + lane * 4);
            uint2 r1 = *(const uint2*)(Hin + (size_t)s1 * DOUT + lane * 4);
            uint2 r2 = *(const uint2*)(Hin + (size_t)s2 * DOUT + lane * 4);
            uint2 r3 = *(const uint2*)(Hin + (size_t)s3 * DOUT + lane * 4);
            v0 += sd; v1 += sd; v2 += sd; v3 += sd;
            v0 = v0 > 0.f ? v0 : 0.2f * v0;
            v1 = v1 > 0.f ? v1 : 0.2f * v1;
            v2 = v2 > 0.f ? v2 : 0.2f * v2;
            v3 = v3 > 0.f ? v3 : 0.2f * v3;
            float e0 = __expf(v0 - m), e1 = __expf(v1 - m);
            float e2 = __expf(v2 - m), e3 = __expf(v3 - m);
            denom += (e0 + e1) + (e2 + e3);
            float2 f0a = __half22float2(*(__half2*)&r0.x), f0b = __half22float2(*(__half2*)&r0.y);
            float2 f1a = __half22float2(*(__half2*)&r1.x), f1b = __half22float2(*(__half2*)&r1.y);
            float2 f2a = __half22float2(*(__half2*)&r2.x), f2b = __half22float2(*(__half2*)&r2.y);
            float2 f3a = __half22float2(*(__half2*)&r3.x), f3b = __half22float2(*(__half2*)&r3.y);
            acc[0] += e0 * f0a.x + e1 * f1a.x + e2 * f2a.x + e3 * f3a.x;
            acc[1] += e0 * f0a.y + e1 * f1a.y + e2 * f2a.y + e3 * f3a.y;
            acc[2] += e0 * f0b.x + e1 * f1b.x + e2 * f2b.x + e3 * f3b.x;
            acc[3] += e0 * f0b.y + e1 * f1b.y + e2 * f2b.y + e3 * f3b.y;
        } else {
            uint32_t r0 = *(const uint32_t*)(Hin + (size_t)s0 * DOUT + lane * 2);
            uint32_t r1 = *(const uint32_t*)(Hin + (size_t)s1 * DOUT + lane * 2);
            uint32_t r2 = *(const uint32_t*)(Hin + (size_t)s2 * DOUT + lane * 2);
            uint32_t r3 = *(const uint32_t*)(Hin + (size_t)s3 * DOUT + lane * 2);
            v0 += sd; v1 += sd; v2 += sd; v3 += sd;
            v0 = v0 > 0.f ? v0 : 0.2f * v0;
            v1 = v1 > 0.f ? v1 : 0.2f * v1;
            v2 = v2 > 0.f ? v2 : 0.2f * v2;
            v3 = v3 > 0.f ? v3 : 0.2f * v3;
            float e0 = __expf(v0 - m), e1 = __expf(v1 - m);
            float e2 = __expf(v2 - m), e3 = __expf(v3 - m);
            denom += (e0 + e1) + (e2 + e3);
            float2 f0 = __half22float2(*(__half2*)&r0);
            float2 f1 = __half22float2(*(__half2*)&r1);
            float2 f2 = __half22float2(*(__half2*)&r2);
            float2 f3 = __half22float2(*(__half2*)&r3);
            acc[0] += e0 * f0.x + e1 * f1.x + e2 * f2.x + e3 * f3.x;
            acc[1] += e0 * f0.y + e1 * f1.y + e2 * f2.y + e3 * f3.y;
        }
    }
    for (; j < end; j++) {
        int s0 = g_col[j];
        float v0 = g_ssrc[s0] + sd;
        v0 = v0 > 0.f ? v0 : 0.2f * v0;
        float e0 = __expf(v0 - m);
        denom += e0;
        if constexpr (V == 4) {
            uint2 r0 = *(const uint2*)(Hin + (size_t)s0 * DOUT + lane * 4);
            float2 f0a = __half22float2(*(__half2*)&r0.x), f0b = __half22float2(*(__half2*)&r0.y);
            acc[0] += e0 * f0a.x; acc[1] += e0 * f0a.y;
            acc[2] += e0 * f0b.x; acc[3] += e0 * f0b.y;
        } else {
            uint32_t r0 = *(const uint32_t*)(Hin + (size_t)s0 * DOUT + lane * 2);
            float2 f0 = __half22float2(*(__half2*)&r0);
            acc[0] += e0 * f0.x; acc[1] += e0 * f0.y;
        }
    }
    float inv = 1.0f / denom;

    if constexpr (!FINAL) {
        if constexpr (V == 4) {
            *(float4*)(out + (size_t)gw * DOUT + lane * 4) =
                make_float4(acc[0] * inv, acc[1] * inv, acc[2] * inv, acc[3] * inv);
        } else {
            *(float2*)(out + (size_t)gw * DOUT + lane * 2) =
                make_float2(acc[0] * inv, acc[1] * inv);
        }
    } else {
        float2 bb = *(const float2*)(bias + lane * 2);
        float x0 = acc[0] * inv + bb.x;
        float x1 = acc[1] * inv + bb.y;
        float mm = fmaxf(x0, x1);
        #pragma unroll
        for (int o = 16; o; o >>= 1) mm = fmaxf(mm, __shfl_xor_sync(0xffffffffu, mm, o));
        float s = __expf(x0 - mm) + __expf(x1 - mm);
        #pragma unroll
        for (int o = 16; o; o >>= 1) s += __shfl_xor_sync(0xffffffffu, s, o);
        float lse = mm + __logf(s);
        *(float2*)(out + (size_t)gw * 64 + lane * 2) = make_float2(x0 - lse, x1 - lse);
    }
}

// ---------------- launch ----------------
extern "C" void kernel_launch(void* const* d_in, const int* in_sizes, int n_in,
                              void* d_out, int out_size)
{
    const float* x   = (const float*)d_in[0];
    const int*   ei  = (const int*)d_in[1];
    const float* W0  = (const float*)d_in[2];
    const float* as0 = (const float*)d_in[3];
    const float* ad0 = (const float*)d_in[4];
    const float* b0  = (const float*)d_in[5];
    const float* W1  = (const float*)d_in[6];
    const float* as1 = (const float*)d_in[7];
    const float* ad1 = (const float*)d_in[8];
    const float* b1  = (const float*)d_in[9];
    const float* W2  = (const float*)d_in[10];
    const float* as2 = (const float*)d_in[11];
    const float* ad2 = (const float*)d_in[12];
    const float* b2  = (const float*)d_in[13];

    int n = in_sizes[0] / HD;
    int E = in_sizes[1] / 2;
    const int* src = ei;
    const int* dst = ei + E;

    __half* h = nullptr;
    float* agg = nullptr;
    uint4 *bf0, *bf1, *bf2;
    cudaGetSymbolAddress((void**)&h, g_h);
    cudaGetSymbolAddress((void**)&agg, g_agg);
    cudaGetSymbolAddress((void**)&bf0, g_bf0);
    cudaGetSymbolAddress((void**)&bf1, g_bf1);
    cudaGetSymbolAddress((void**)&bf2, g_bf2);

    const int smemA = 2 * 128 * 136 * 2;   // 69632 bytes
    cudaFuncSetAttribute(gemm_mma<128, false>, cudaFuncAttributeMaxDynamicSharedMemorySize, smemA);
    cudaFuncSetAttribute(gemm_mma<128, true>,  cudaFuncAttributeMaxDynamicSharedMemorySize, smemA);
    cudaFuncSetAttribute(gemm_mma<64, true>,   cudaFuncAttributeMaxDynamicSharedMemorySize, smemA);

    wprep_kernel<<<40, 256>>>(W0, W1, W2);

    int nb = (n + 255) / 256;
    zero_kernel<<<(n + 255) / 256, 256>>>(n);
    hist_kernel<<<(E / 4 + 255) / 256, 256>>>(dst, E);
    scan_reduce<<<nb, 256>>>(n);
    scan_bsums<<<1, 256>>>(nb, n);
    scan_write<<<nb, 256>>>(n);
    fill_kernel<<<((E + n + 3) / 4 + 255) / 256, 256>>>(src, dst, E, n);

    int gemmg = (n + 127) / 128;
    int warpg = (n * 32 + 255) / 256;

    gemm_mma<128, false><<<gemmg, 256, smemA>>>(x, bf0, nullptr, as0, ad0, h, n);
    agg_kernel<128, false><<<warpg, 256>>>(h, agg, nullptr, n);

    gemm_mma<128, true><<<gemmg, 256, smemA>>>(agg, bf1, b0, as1, ad1, h, n);
    agg_kernel<128, false><<<warpg, 256>>>(h, agg, nullptr, n);

    gemm_mma<64, true><<<gemmg, 256, smemA>>>(agg, bf2, b1, as2, ad2, h, n);
    agg_kernel<64, true><<<warpg, 256>>>(h, (float*)d_out, b2, n);
}